// round 15
// baseline (speedup 1.0000x reference)
#include <cuda_runtime.h>
#include <cuda_fp16.h>
#include <mma.h>
#include <cstdint>

using namespace nvcuda;

// Problem constants
#define BB   2
#define LL   2048
#define DD   512
#define KK   32
#define GG   32
#define HH   8
#define DHH  64
#define CTX  65        // 1 + K + G
#define BL   (BB*LL)   // 4096

// Scratch buffers (device globals: no allocation allowed)
__device__ __half g_Qh   [BL * DD];
__device__ __half g_Kh   [BL * DD];
__device__ __half g_Vh   [BL * DD];
__device__ __half g_attnh[BL * DD];          // attention output (fp16)
__device__ __half g_Kgh  [BB * GG * DD];
__device__ __half g_Vgh  [BB * GG * DD];
// fp16 copies of GEMM inputs
__device__ __half g_sp_h[BL * DD];
__device__ __half g_gl_h[BB * GG * DD];
__device__ __half g_Wq_h[DD * DD];
__device__ __half g_Wk_h[DD * DD];
__device__ __half g_Wv_h[DD * DD];
__device__ __half g_Wo_h[DD * DD];

// Streams/events for the skewed two-chain pipeline (created once, pre-checkpoint).
static struct StreamHolder {
    cudaStream_t s1 = nullptr;
    cudaEvent_t  evF = nullptr, evQ = nullptr, evJ = nullptr;
    StreamHolder() {
        cudaStreamCreateWithFlags(&s1, cudaStreamNonBlocking);
        cudaEventCreateWithFlags(&evF, cudaEventDisableTiming);
        cudaEventCreateWithFlags(&evQ, cudaEventDisableTiming);
        cudaEventCreateWithFlags(&evJ, cudaEventDisableTiming);
    }
} g_str;

// ---------------------------------------------------------------------------
// fp32 -> fp16 converter for all 6 GEMM inputs (blockIdx.y selects segment)
// n counts are in float4 (4-element) units.
// ---------------------------------------------------------------------------
__global__ __launch_bounds__(256)
void to_half_all(const float* s0, __half* d0, int n0,
                 const float* s1, __half* d1, int n1,
                 const float* s2, __half* d2, int n2,
                 const float* s3, __half* d3, int n3,
                 const float* s4, __half* d4, int n4,
                 const float* s5, __half* d5, int n5)
{
    const float* src; __half* dst; int n;
    switch (blockIdx.y) {
        case 0: src = s0; dst = d0; n = n0; break;
        case 1: src = s1; dst = d1; n = n1; break;
        case 2: src = s2; dst = d2; n = n2; break;
        case 3: src = s3; dst = d3; n = n3; break;
        case 4: src = s4; dst = d4; n = n4; break;
        default: src = s5; dst = d5; n = n5; break;
    }
    int stride = gridDim.x * blockDim.x;
    for (int i = blockIdx.x * blockDim.x + threadIdx.x; i < n; i += stride) {
        float4 v = reinterpret_cast<const float4*>(src)[i];
        __half2* d2p = reinterpret_cast<__half2*>(dst) + i * 2;
        d2p[0] = __floats2half2_rn(v.x, v.y);
        d2p[1] = __floats2half2_rn(v.z, v.w);
    }
}

// ---------------------------------------------------------------------------
// cp.async helpers
// ---------------------------------------------------------------------------
__device__ __forceinline__ void cp_async16(void* smem_dst, const void* gsrc) {
    unsigned int sa = (unsigned int)__cvta_generic_to_shared(smem_dst);
    asm volatile("cp.async.cg.shared.global [%0], [%1], 16;\n" :: "r"(sa), "l"(gsrc));
}
__device__ __forceinline__ void cp_commit() {
    asm volatile("cp.async.commit_group;\n" ::);
}
template <int N>
__device__ __forceinline__ void cp_wait() {
    asm volatile("cp.async.wait_group %0;\n" :: "n"(N));
}

// ---------------------------------------------------------------------------
// fp16 GEMM core (R11 proven config):
// C[0:64, n0:n0+128] = A[0:64, 0:512] @ W[512,512]
// BM=64, BN=128, BK=32, 3-stage cp.async pipeline, 128 threads (4 warps 2x2),
// warp tile 32x64 (2x4 wmma fp16 m16n16k16, fp32 accum). 4 CTAs/SM.
// ---------------------------------------------------------------------------
constexpr int ASTR_H = 40;    // As row stride (halves): 32 + 8 pad
constexpr int BSTR_H = 136;   // Bs row stride (halves): 128 + 8 pad
constexpr int STAGE_HALVES = 64 * ASTR_H + 32 * BSTR_H;    // 6912
constexpr int GEMM_SMEM = 3 * STAGE_HALVES * 2;            // 41472 bytes
constexpr int CSTR = 132;     // epilogue float staging stride

__device__ __forceinline__ void issue_stage_h(
    __half* stage, const __half* __restrict__ A, const __half* __restrict__ W,
    int n0, int k0, int tid)
{
    __half* As = stage;
    __half* Bs = stage + 64 * ASTR_H;
    #pragma unroll
    for (int t = 0; t < 2; t++) {                 // A: 64 rows x 4 chunks(8h)
        int j = tid + t * 128;
        int r = j >> 2, c = (j & 3) << 3;
        cp_async16(&As[r * ASTR_H + c], &A[(size_t)r * 512 + k0 + c]);
    }
    #pragma unroll
    for (int t = 0; t < 4; t++) {                 // B: 32 rows x 16 chunks(8h)
        int j = tid + t * 128;
        int rb = j >> 4, cb = (j & 15) << 3;
        cp_async16(&Bs[rb * BSTR_H + cb], &W[(size_t)(k0 + rb) * 512 + n0 + cb]);
    }
}

__device__ __forceinline__ void gemm_core_h(
    const __half* __restrict__ A, const __half* __restrict__ W,
    float* __restrict__ Cf, __half* __restrict__ Ch,
    const float* __restrict__ bias, int n0)
{
    extern __shared__ __align__(16) __half hsmem[];
    const int tid    = threadIdx.x;
    const int wid    = tid >> 5;
    const int warp_m = wid >> 1;     // 0..1 -> rows warp_m*32
    const int warp_n = wid & 1;      // 0..1 -> cols warp_n*64

    wmma::fragment<wmma::accumulator, 16, 16, 16, float> acc[2][4];
    #pragma unroll
    for (int i = 0; i < 2; i++)
        #pragma unroll
        for (int j = 0; j < 4; j++)
            wmma::fill_fragment(acc[i][j], 0.0f);

    #pragma unroll
    for (int s = 0; s < 2; s++) {
        issue_stage_h(hsmem + s * STAGE_HALVES, A, W, n0, s * 32, tid);
        cp_commit();
    }

    for (int it = 0; it < 16; it++) {
        cp_wait<1>();          // stage `it` resident
        __syncthreads();       // also guards buffer (it+2)%3 reuse
        if (it + 2 < 16)
            issue_stage_h(hsmem + ((it + 2) % 3) * STAGE_HALVES, A, W,
                          n0, (it + 2) * 32, tid);
        cp_commit();           // one group per iter keeps counts aligned

        __half* As = hsmem + (it % 3) * STAGE_HALVES;
        __half* Bs = As + 64 * ASTR_H;
        #pragma unroll
        for (int ks = 0; ks < 2; ks++) {
            wmma::fragment<wmma::matrix_a, 16, 16, 16, half, wmma::row_major> af[2];
            wmma::fragment<wmma::matrix_b, 16, 16, 16, half, wmma::row_major> bf[4];
            wmma::load_matrix_sync(af[0], &As[(warp_m * 32     ) * ASTR_H + ks * 16], ASTR_H);
            wmma::load_matrix_sync(af[1], &As[(warp_m * 32 + 16) * ASTR_H + ks * 16], ASTR_H);
            #pragma unroll
            for (int j = 0; j < 4; j++)
                wmma::load_matrix_sync(bf[j], &Bs[(ks * 16) * BSTR_H + warp_n * 64 + j * 16], BSTR_H);
            #pragma unroll
            for (int i = 0; i < 2; i++)
                #pragma unroll
                for (int j = 0; j < 4; j++)
                    wmma::mma_sync(acc[i][j], af[i], bf[j], acc[i][j]);
        }
    }
    __syncthreads();   // all compute done before epilogue smem reuse

    // Stage via smem (reuse pipeline buffer as float[64][CSTR])
    float (*Cs)[CSTR] = reinterpret_cast<float(*)[CSTR]>(hsmem);
    #pragma unroll
    for (int i = 0; i < 2; i++)
        #pragma unroll
        for (int j = 0; j < 4; j++)
            wmma::store_matrix_sync(
                &Cs[warp_m * 32 + i * 16][warp_n * 64 + j * 16],
                acc[i][j], CSTR, wmma::mem_row_major);
    __syncthreads();

    const int n4 = 64 * 32;                // 64 rows x 128 floats in float4 units
    if (Ch != nullptr) {
        for (int lin = tid; lin < n4; lin += 128) {
            int r = lin >> 5, c4 = (lin & 31) << 2;
            float4 v = *reinterpret_cast<const float4*>(&Cs[r][c4]);
            __half2* dst = reinterpret_cast<__half2*>(&Ch[(size_t)r * 512 + n0 + c4]);
            dst[0] = __floats2half2_rn(v.x, v.y);
            dst[1] = __floats2half2_rn(v.z, v.w);
        }
    } else {
        for (int lin = tid; lin < n4; lin += 128) {
            int r = lin >> 5, c4 = (lin & 31) << 2;
            float4 v = *reinterpret_cast<const float4*>(&Cs[r][c4]);
            v.x += bias[n0 + c4 + 0];
            v.y += bias[n0 + c4 + 1];
            v.z += bias[n0 + c4 + 2];
            v.w += bias[n0 + c4 + 3];
            *reinterpret_cast<float4*>(&Cf[(size_t)r * 512 + n0 + c4]) = v;
        }
    }
}

// Per-batch Q/K/V projection (+ glat K/V duplicated per chain).
// grid = (4, 33, 3): y<32 -> spatial tile (ybase+y); y==32 -> glat (64 rows).
__global__ __launch_bounds__(128, 4)
void qkv_gemm(const __half* __restrict__ spatial, const __half* __restrict__ glat,
              const __half* __restrict__ Wq, const __half* __restrict__ Wk,
              const __half* __restrict__ Wv,
              __half* __restrict__ Q, __half* __restrict__ K, __half* __restrict__ V,
              __half* __restrict__ Kg, __half* __restrict__ Vg, int ybase)
{
    const int z = blockIdx.z, y = blockIdx.y;
    const __half* W = (z == 0) ? Wq : (z == 1) ? Wk : Wv;
    if (y < 32) {
        const int tile = ybase + y;
        const __half* A = spatial + (size_t)tile * 64 * 512;
        __half* C = ((z == 0) ? Q : (z == 1) ? K : V) + (size_t)tile * 64 * 512;
        gemm_core_h(A, W, nullptr, C, nullptr, blockIdx.x * 128);
    } else {
        if (z == 0) return;
        gemm_core_h(glat, W, nullptr, (z == 1) ? Kg : Vg, nullptr,
                    blockIdx.x * 128);
    }
}

// Per-batch output projection with bias. grid = (4, 32)
__global__ __launch_bounds__(128, 4)
void out_gemm(const __half* __restrict__ A, const __half* __restrict__ W,
              const float* __restrict__ bias, float* __restrict__ C, int ybase)
{
    const int tile = ybase + blockIdx.y;
    gemm_core_h(A + (size_t)tile * 64 * 512, W,
                C + (size_t)tile * 64 * 512, nullptr, bias,
                blockIdx.x * 128);
}

// ---------------------------------------------------------------------------
// Gather attention: one block per (b,l), one warp per head.
// 8-lane groups: each group handles one context with 16B (8-half) loads.
// blbase selects the batch's 2048-query slab.
// ---------------------------------------------------------------------------
__global__ __launch_bounds__(256)
void attn_kernel(const __half* __restrict__ Q,   const __half* __restrict__ Ksp,
                 const __half* __restrict__ Vsp, const __half* __restrict__ Kg,
                 const __half* __restrict__ Vg,  const int*    __restrict__ topk,
                 const float*  __restrict__ dist,
                 const float*  __restrict__ log_sigma,
                 const float*  __restrict__ gbias_p,
                 __half* __restrict__ outh, int blbase)
{
    const int bl   = blbase + blockIdx.x;
    const int b    = bl >> 11;            // L = 2048
    const int tid  = threadIdx.x;
    const int h    = tid >> 5;
    const int lane = tid & 31;
    const int g    = lane >> 3;           // group 0..3
    const int s    = lane & 7;            // sublane 0..7

    __shared__ const __half* kp[CTX];
    __shared__ const __half* vp[CTX];
    __shared__ float dist2[33];
    __shared__ float logits[HH][68];

    if (tid < CTX) {
        int c = tid;
        const __half *kq, *vq;
        if (c == 0) {
            kq = Ksp + (size_t)bl * DD;
            vq = Vsp + (size_t)bl * DD;
        } else if (c < 33) {
            int r = b * LL + topk[(size_t)bl * KK + (c - 1)];
            kq = Ksp + (size_t)r * DD;
            vq = Vsp + (size_t)r * DD;
        } else {
            int r = b * GG + (c - 33);
            kq = Kg + (size_t)r * DD;
            vq = Vg + (size_t)r * DD;
        }
        kp[c] = kq;
        vp[c] = vq;
        if (c < 33) {
            float d = (c == 0) ? 0.0f : dist[(size_t)bl * KK + (c - 1)];
            dist2[c] = d * d;
        }
    }
    __syncthreads();

    const float inv2s = 0.5f * __expf(-2.0f * log_sigma[h]);  // 1/(2*sigma^2)
    const float gb    = *gbias_p;
    const float scale = 0.125f;                               // 64^-0.5
    const int   off   = h * DHH + s * 8;    // 8-half slice for this sublane

    // Q slice: 8 halves -> 8 floats
    float qf[8];
    {
        float4 qv = *reinterpret_cast<const float4*>(Q + (size_t)bl * DD + off);
        const __half2* qh = reinterpret_cast<const __half2*>(&qv);
        #pragma unroll
        for (int i = 0; i < 4; i++) {
            float2 f = __half22float2(qh[i]);
            qf[2 * i]     = f.x;
            qf[2 * i + 1] = f.y;
        }
    }

    // Logits: 4 contexts per iteration (one per 8-lane group)
    #pragma unroll 4
    for (int c0 = 0; c0 < CTX; c0 += 4) {
        int  c     = c0 + g;
        bool valid = (c < CTX);
        float dot = 0.0f;
        if (valid) {
            float4 kv = *reinterpret_cast<const float4*>(kp[c] + off);
            const __half2* kh = reinterpret_cast<const __half2*>(&kv);
            #pragma unroll
            for (int i = 0; i < 4; i++) {
                float2 f = __half22float2(kh[i]);
                dot += qf[2 * i] * f.x + qf[2 * i + 1] * f.y;
            }
        }
        #pragma unroll
        for (int d = 4; d; d >>= 1)
            dot += __shfl_xor_sync(0xffffffffu, dot, d);
        if (s == 0 && valid)
            logits[h][c] = dot * scale + ((c < 33) ? -dist2[c] * inv2s : gb);
    }
    __syncwarp();

    // softmax over 65 entries (per-warp)
    float l0 = logits[h][lane];
    float l1 = logits[h][lane + 32];
    float l2 = (lane == 0) ? logits[h][64] : -1e30f;
    float m = fmaxf(fmaxf(l0, l1), l2);
    #pragma unroll
    for (int d = 16; d; d >>= 1)
        m = fmaxf(m, __shfl_xor_sync(0xffffffffu, m, d));
    float e0 = __expf(l0 - m);
    float e1 = __expf(l1 - m);
    float e2 = (lane == 0) ? __expf(l2 - m) : 0.0f;
    float sm = e0 + e1 + e2;
    #pragma unroll
    for (int d = 16; d; d >>= 1)
        sm += __shfl_xor_sync(0xffffffffu, sm, d);
    float inv = 1.0f / sm;
    logits[h][lane]      = e0 * inv;
    logits[h][lane + 32] = e1 * inv;
    if (lane == 0) logits[h][64] = e2 * inv;
    __syncwarp();

    // Weighted V sum: group g handles contexts c = 4*i + g; lane holds 8 dims.
    float acc[8];
    #pragma unroll
    for (int i = 0; i < 8; i++) acc[i] = 0.0f;

    #pragma unroll 4
    for (int i = 0; i < 17; i++) {
        int c = 4 * i + g;
        if (c < CTX) {
            float  p  = logits[h][c];
            float4 vv = *reinterpret_cast<const float4*>(vp[c] + off);
            const __half2* vh = reinterpret_cast<const __half2*>(&vv);
            #pragma unroll
            for (int k = 0; k < 4; k++) {
                float2 f = __half22float2(vh[k]);
                acc[2 * k]     += p * f.x;
                acc[2 * k + 1] += p * f.y;
            }
        }
    }
    // Reduce across the 4 groups (same dims, different contexts)
    #pragma unroll
    for (int k = 0; k < 8; k++) {
        acc[k] += __shfl_xor_sync(0xffffffffu, acc[k], 8);
        acc[k] += __shfl_xor_sync(0xffffffffu, acc[k], 16);
    }
    if (g == 0) {
        __half2 hv[4];
        #pragma unroll
        for (int k = 0; k < 4; k++)
            hv[k] = __floats2half2_rn(acc[2 * k], acc[2 * k + 1]);
        *reinterpret_cast<uint4*>(outh + (size_t)bl * DD + off) =
            *reinterpret_cast<const uint4*>(hv);
    }
}

// ---------------------------------------------------------------------------
extern "C" void kernel_launch(void* const* d_in, const int* in_sizes, int n_in,
                              void* d_out, int out_size)
{
    const float* spatial = (const float*)d_in[0];
    const int*   topk    = (const int*)  d_in[1];
    const float* dist    = (const float*)d_in[2];
    const float* glat    = (const float*)d_in[3];
    const float* Wq      = (const float*)d_in[4];
    const float* Wk      = (const float*)d_in[5];
    const float* Wv      = (const float*)d_in[6];
    const float* Wo      = (const float*)d_in[7];
    const float* bo      = (const float*)d_in[8];
    const float* lsig    = (const float*)d_in[9];
    const float* gbias   = (const float*)d_in[10];
    float* out = (float*)d_out;

    __half *Qp, *Kp, *Vp, *Ah, *Kgp, *Vgp;
    __half *sph, *glh, *wqh, *wkh, *wvh, *woh;
    cudaGetSymbolAddress((void**)&Qp,  g_Qh);
    cudaGetSymbolAddress((void**)&Kp,  g_Kh);
    cudaGetSymbolAddress((void**)&Vp,  g_Vh);
    cudaGetSymbolAddress((void**)&Ah,  g_attnh);
    cudaGetSymbolAddress((void**)&Kgp, g_Kgh);
    cudaGetSymbolAddress((void**)&Vgp, g_Vgh);
    cudaGetSymbolAddress((void**)&sph, g_sp_h);
    cudaGetSymbolAddress((void**)&glh, g_gl_h);
    cudaGetSymbolAddress((void**)&wqh, g_Wq_h);
    cudaGetSymbolAddress((void**)&wkh, g_Wk_h);
    cudaGetSymbolAddress((void**)&wvh, g_Wv_h);
    cudaGetSymbolAddress((void**)&woh, g_Wo_h);

    cudaFuncSetAttribute(qkv_gemm, cudaFuncAttributeMaxDynamicSharedMemorySize, GEMM_SMEM);
    cudaFuncSetAttribute(out_gemm, cudaFuncAttributeMaxDynamicSharedMemorySize, GEMM_SMEM);

    // Identify the stream our <<<>>> launches target (the captured one during
    // capture; legacy otherwise).
    cudaStreamCaptureStatus stL = cudaStreamCaptureStatusNone;
    cudaStreamCaptureStatus stP = cudaStreamCaptureStatusNone;
    cudaStreamIsCapturing(cudaStreamLegacy, &stL);
    cudaStreamIsCapturing(cudaStreamPerThread, &stP);
    cudaStream_t smain = (stP == cudaStreamCaptureStatusActive &&
                          stL != cudaStreamCaptureStatusActive)
                         ? cudaStreamPerThread : cudaStreamLegacy;
    cudaStream_t s1 = g_str.s1;

    // Convert all GEMM inputs to fp16 (one pass), then fork.
    dim3 cvt_grid(64, 6);
    to_half_all<<<cvt_grid, 256, 0, smain>>>(
        spatial, sph, BL * DD / 4,
        Wq, wqh, DD * DD / 4,
        Wk, wkh, DD * DD / 4,
        Wv, wvh, DD * DD / 4,
        Wo, woh, DD * DD / 4,
        glat, glh, BB * GG * DD / 4);
    cudaEventRecord(g_str.evF, smain);
    cudaStreamWaitEvent(s1, g_str.evF, 0);

    dim3 qkv_grid(4, 33, 3);
    dim3 out_grid(4, 32);

    // Chain 0 (batch 0) on smain.
    qkv_gemm<<<qkv_grid, 128, GEMM_SMEM, smain>>>(
        sph, glh, wqh, wkh, wvh, Qp, Kp, Vp, Kgp, Vgp, 0);
    cudaEventRecord(g_str.evQ, smain);        // skew point: qkv0 done
    attn_kernel<<<2048, 256, 0, smain>>>(
        Qp, Kp, Vp, Kgp, Vgp, topk, dist, lsig, gbias, Ah, 0);
    out_gemm<<<out_grid, 128, GEMM_SMEM, smain>>>(
        Ah, woh, bo, out, 0);

    // Chain 1 (batch 1) on s1, skewed one phase: qkv1 starts after qkv0,
    // so qkv1 overlaps attn0, attn1 overlaps out0.
    cudaStreamWaitEvent(s1, g_str.evQ, 0);
    qkv_gemm<<<qkv_grid, 128, GEMM_SMEM, s1>>>(
        sph, glh, wqh, wkh, wvh, Qp, Kp, Vp, Kgp, Vgp, 32);
    attn_kernel<<<2048, 256, 0, s1>>>(
        Qp, Kp, Vp, Kgp, Vgp, topk, dist, lsig, gbias, Ah, 2048);
    out_gemm<<<out_grid, 128, GEMM_SMEM, s1>>>(
        Ah, woh, bo, out, 32);

    // Join chain-1 back into the main stream.
    cudaEventRecord(g_str.evJ, s1);
    cudaStreamWaitEvent(smain, g_str.evJ, 0);
}

// round 16
// speedup vs baseline: 1.0914x; 1.0914x over previous
#include <cuda_runtime.h>
#include <cuda_fp16.h>
#include <mma.h>
#include <cstdint>

using namespace nvcuda;

// Problem constants
#define BB   2
#define LL   2048
#define DD   512
#define KK   32
#define GG   32
#define HH   8
#define DHH  64
#define CTX  65        // 1 + K + G
#define BL   (BB*LL)   // 4096

// Scratch buffers (device globals: no allocation allowed)
__device__ __half g_Qh   [BL * DD];
__device__ __half g_Kh   [BL * DD];
__device__ __half g_Vh   [BL * DD];
__device__ __half g_attnh[BL * DD];          // attention output (fp16)
__device__ __half g_Kgh  [BB * GG * DD];
__device__ __half g_Vgh  [BB * GG * DD];
// fp16 copies of GEMM inputs
__device__ __half g_sp_h[BL * DD];
__device__ __half g_gl_h[BB * GG * DD];
__device__ __half g_Wq_h[DD * DD];
__device__ __half g_Wk_h[DD * DD];
__device__ __half g_Wv_h[DD * DD];
__device__ __half g_Wo_h[DD * DD];

// Streams/events for the two-chain fork-join (created once, pre-checkpoint).
static struct StreamHolder {
    cudaStream_t s1 = nullptr;
    cudaEvent_t  evF = nullptr, evJ = nullptr;
    StreamHolder() {
        cudaStreamCreateWithFlags(&s1, cudaStreamNonBlocking);
        cudaEventCreateWithFlags(&evF, cudaEventDisableTiming);
        cudaEventCreateWithFlags(&evJ, cudaEventDisableTiming);
    }
} g_str;

// ---------------------------------------------------------------------------
// fp32 -> fp16 converter for all 6 GEMM inputs (blockIdx.y selects segment)
// n counts are in float4 (4-element) units.
// ---------------------------------------------------------------------------
__global__ __launch_bounds__(256)
void to_half_all(const float* s0, __half* d0, int n0,
                 const float* s1, __half* d1, int n1,
                 const float* s2, __half* d2, int n2,
                 const float* s3, __half* d3, int n3,
                 const float* s4, __half* d4, int n4,
                 const float* s5, __half* d5, int n5)
{
    const float* src; __half* dst; int n;
    switch (blockIdx.y) {
        case 0: src = s0; dst = d0; n = n0; break;
        case 1: src = s1; dst = d1; n = n1; break;
        case 2: src = s2; dst = d2; n = n2; break;
        case 3: src = s3; dst = d3; n = n3; break;
        case 4: src = s4; dst = d4; n = n4; break;
        default: src = s5; dst = d5; n = n5; break;
    }
    int stride = gridDim.x * blockDim.x;
    for (int i = blockIdx.x * blockDim.x + threadIdx.x; i < n; i += stride) {
        float4 v = reinterpret_cast<const float4*>(src)[i];
        __half2* d2p = reinterpret_cast<__half2*>(dst) + i * 2;
        d2p[0] = __floats2half2_rn(v.x, v.y);
        d2p[1] = __floats2half2_rn(v.z, v.w);
    }
}

// ---------------------------------------------------------------------------
// cp.async helpers
// ---------------------------------------------------------------------------
__device__ __forceinline__ void cp_async16(void* smem_dst, const void* gsrc) {
    unsigned int sa = (unsigned int)__cvta_generic_to_shared(smem_dst);
    asm volatile("cp.async.cg.shared.global [%0], [%1], 16;\n" :: "r"(sa), "l"(gsrc));
}
__device__ __forceinline__ void cp_commit() {
    asm volatile("cp.async.commit_group;\n" ::);
}
template <int N>
__device__ __forceinline__ void cp_wait() {
    asm volatile("cp.async.wait_group %0;\n" :: "n"(N));
}

// ---------------------------------------------------------------------------
// fp16 GEMM core: C[0:rows, n0:n0+128] = A[0:rows, 0:512] @ W[512,512]
// BM=128, BN=128, BK=32, 3-stage cp.async pipeline, 128 threads (4 warps 2x2),
// warp tile 64x64 (4x4 wmma fp16 m16n16k16, fp32 accum) -> 0.5 frag-loads/MMA.
// 2 CTAs/SM.
// ---------------------------------------------------------------------------
constexpr int ASTR_H = 40;    // As row stride (halves): 32 + 8 pad
constexpr int BSTR_H = 136;   // Bs row stride (halves): 128 + 8 pad
constexpr int STAGE_HALVES = 128 * ASTR_H + 32 * BSTR_H;   // 9472
constexpr int PIPE_BYTES = 3 * STAGE_HALVES * 2;           // 56832
constexpr int CSTR = 132;     // epilogue float staging stride
constexpr int EPI_BYTES = 128 * CSTR * 4;                  // 67584
constexpr int GEMM_SMEM = EPI_BYTES;                       // max(pipe, epi)

__device__ __forceinline__ void issue_stage_h(
    __half* stage, const __half* __restrict__ A, const __half* __restrict__ W,
    int n0, int k0, int tid, int rmask)
{
    __half* As = stage;
    __half* Bs = stage + 128 * ASTR_H;
    #pragma unroll
    for (int t = 0; t < 4; t++) {                 // A: 128 rows x 4 chunks(8h)
        int j = tid + t * 128;
        int r = j >> 2, c = (j & 3) << 3;
        cp_async16(&As[r * ASTR_H + c], &A[(size_t)(r & rmask) * 512 + k0 + c]);
    }
    #pragma unroll
    for (int t = 0; t < 4; t++) {                 // B: 32 rows x 16 chunks(8h)
        int j = tid + t * 128;
        int rb = j >> 4, cb = (j & 15) << 3;
        cp_async16(&Bs[rb * BSTR_H + cb], &W[(size_t)(k0 + rb) * 512 + n0 + cb]);
    }
}

__device__ __forceinline__ void gemm_core_h(
    const __half* __restrict__ A, const __half* __restrict__ W,
    float* __restrict__ Cf, __half* __restrict__ Ch,
    const float* __restrict__ bias, int n0, int rows)
{
    extern __shared__ __align__(16) __half hsmem[];
    const int tid    = threadIdx.x;
    const int wid    = tid >> 5;
    const int warp_m = wid >> 1;     // 0..1 -> rows warp_m*64
    const int warp_n = wid & 1;      // 0..1 -> cols warp_n*64
    const int rmask  = (rows == 64) ? 63 : 127;

    wmma::fragment<wmma::accumulator, 16, 16, 16, float> acc[4][4];
    #pragma unroll
    for (int i = 0; i < 4; i++)
        #pragma unroll
        for (int j = 0; j < 4; j++)
            wmma::fill_fragment(acc[i][j], 0.0f);

    #pragma unroll
    for (int s = 0; s < 2; s++) {
        issue_stage_h(hsmem + s * STAGE_HALVES, A, W, n0, s * 32, tid, rmask);
        cp_commit();
    }

    for (int it = 0; it < 16; it++) {
        cp_wait<1>();          // stage `it` resident
        __syncthreads();       // also guards buffer (it+2)%3 reuse
        if (it + 2 < 16)
            issue_stage_h(hsmem + ((it + 2) % 3) * STAGE_HALVES, A, W,
                          n0, (it + 2) * 32, tid, rmask);
        cp_commit();           // one group per iter keeps counts aligned

        __half* As = hsmem + (it % 3) * STAGE_HALVES;
        __half* Bs = As + 128 * ASTR_H;
        #pragma unroll
        for (int ks = 0; ks < 2; ks++) {
            wmma::fragment<wmma::matrix_a, 16, 16, 16, half, wmma::row_major> af[4];
            wmma::fragment<wmma::matrix_b, 16, 16, 16, half, wmma::row_major> bf[4];
            #pragma unroll
            for (int i = 0; i < 4; i++)
                wmma::load_matrix_sync(af[i],
                    &As[(warp_m * 64 + i * 16) * ASTR_H + ks * 16], ASTR_H);
            #pragma unroll
            for (int j = 0; j < 4; j++)
                wmma::load_matrix_sync(bf[j],
                    &Bs[(ks * 16) * BSTR_H + warp_n * 64 + j * 16], BSTR_H);
            #pragma unroll
            for (int i = 0; i < 4; i++)
                #pragma unroll
                for (int j = 0; j < 4; j++)
                    wmma::mma_sync(acc[i][j], af[i], bf[j], acc[i][j]);
        }
    }
    __syncthreads();   // all compute done before epilogue smem reuse

    // Stage via smem (reuse pipeline buffer as float[128][CSTR])
    float (*Cs)[CSTR] = reinterpret_cast<float(*)[CSTR]>(hsmem);
    #pragma unroll
    for (int i = 0; i < 4; i++)
        #pragma unroll
        for (int j = 0; j < 4; j++)
            wmma::store_matrix_sync(
                &Cs[warp_m * 64 + i * 16][warp_n * 64 + j * 16],
                acc[i][j], CSTR, wmma::mem_row_major);
    __syncthreads();

    const int n4 = rows * 32;              // rows x 128 floats in float4 units
    if (Ch != nullptr) {
        for (int lin = tid; lin < n4; lin += 128) {
            int r = lin >> 5, c4 = (lin & 31) << 2;
            float4 v = *reinterpret_cast<const float4*>(&Cs[r][c4]);
            __half2* dst = reinterpret_cast<__half2*>(&Ch[(size_t)r * 512 + n0 + c4]);
            dst[0] = __floats2half2_rn(v.x, v.y);
            dst[1] = __floats2half2_rn(v.z, v.w);
        }
    } else {
        for (int lin = tid; lin < n4; lin += 128) {
            int r = lin >> 5, c4 = (lin & 31) << 2;
            float4 v = *reinterpret_cast<const float4*>(&Cs[r][c4]);
            v.x += bias[n0 + c4 + 0];
            v.y += bias[n0 + c4 + 1];
            v.z += bias[n0 + c4 + 2];
            v.w += bias[n0 + c4 + 3];
            *reinterpret_cast<float4*>(&Cf[(size_t)r * 512 + n0 + c4]) = v;
        }
    }
}

// Per-batch Q/K/V projection (+ glat K/V duplicated per chain).
// grid = (4, 17, 3): y<16 -> 128-row spatial tile (ybase+y); y==16 -> glat.
__global__ __launch_bounds__(128, 2)
void qkv_gemm(const __half* __restrict__ spatial, const __half* __restrict__ glat,
              const __half* __restrict__ Wq, const __half* __restrict__ Wk,
              const __half* __restrict__ Wv,
              __half* __restrict__ Q, __half* __restrict__ K, __half* __restrict__ V,
              __half* __restrict__ Kg, __half* __restrict__ Vg, int ybase)
{
    const int z = blockIdx.z, y = blockIdx.y;
    const __half* W = (z == 0) ? Wq : (z == 1) ? Wk : Wv;
    if (y < 16) {
        const int tile = ybase + y;
        const __half* A = spatial + (size_t)tile * 128 * 512;
        __half* C = ((z == 0) ? Q : (z == 1) ? K : V) + (size_t)tile * 128 * 512;
        gemm_core_h(A, W, nullptr, C, nullptr, blockIdx.x * 128, 128);
    } else {
        if (z == 0) return;
        gemm_core_h(glat, W, nullptr, (z == 1) ? Kg : Vg, nullptr,
                    blockIdx.x * 128, 64);
    }
}

// Per-batch output projection with bias. grid = (4, 16)
__global__ __launch_bounds__(128, 2)
void out_gemm(const __half* __restrict__ A, const __half* __restrict__ W,
              const float* __restrict__ bias, float* __restrict__ C, int ybase)
{
    const int tile = ybase + blockIdx.y;
    gemm_core_h(A + (size_t)tile * 128 * 512, W,
                C + (size_t)tile * 128 * 512, nullptr, bias,
                blockIdx.x * 128, 128);
}

// ---------------------------------------------------------------------------
// Gather attention: one block per (b,l), one warp per head.
// 8-lane groups: each group handles one context with 16B (8-half) loads.
// blbase selects the batch's 2048-query slab.
// ---------------------------------------------------------------------------
__global__ __launch_bounds__(256)
void attn_kernel(const __half* __restrict__ Q,   const __half* __restrict__ Ksp,
                 const __half* __restrict__ Vsp, const __half* __restrict__ Kg,
                 const __half* __restrict__ Vg,  const int*    __restrict__ topk,
                 const float*  __restrict__ dist,
                 const float*  __restrict__ log_sigma,
                 const float*  __restrict__ gbias_p,
                 __half* __restrict__ outh, int blbase)
{
    const int bl   = blbase + blockIdx.x;
    const int b    = bl >> 11;            // L = 2048
    const int tid  = threadIdx.x;
    const int h    = tid >> 5;
    const int lane = tid & 31;
    const int g    = lane >> 3;           // group 0..3
    const int s    = lane & 7;            // sublane 0..7

    __shared__ const __half* kp[CTX];
    __shared__ const __half* vp[CTX];
    __shared__ float dist2[33];
    __shared__ float logits[HH][68];

    if (tid < CTX) {
        int c = tid;
        const __half *kq, *vq;
        if (c == 0) {
            kq = Ksp + (size_t)bl * DD;
            vq = Vsp + (size_t)bl * DD;
        } else if (c < 33) {
            int r = b * LL + topk[(size_t)bl * KK + (c - 1)];
            kq = Ksp + (size_t)r * DD;
            vq = Vsp + (size_t)r * DD;
        } else {
            int r = b * GG + (c - 33);
            kq = Kg + (size_t)r * DD;
            vq = Vg + (size_t)r * DD;
        }
        kp[c] = kq;
        vp[c] = vq;
        if (c < 33) {
            float d = (c == 0) ? 0.0f : dist[(size_t)bl * KK + (c - 1)];
            dist2[c] = d * d;
        }
    }
    __syncthreads();

    const float inv2s = 0.5f * __expf(-2.0f * log_sigma[h]);  // 1/(2*sigma^2)
    const float gb    = *gbias_p;
    const float scale = 0.125f;                               // 64^-0.5
    const int   off   = h * DHH + s * 8;    // 8-half slice for this sublane

    // Q slice: 8 halves -> 8 floats
    float qf[8];
    {
        float4 qv = *reinterpret_cast<const float4*>(Q + (size_t)bl * DD + off);
        const __half2* qh = reinterpret_cast<const __half2*>(&qv);
        #pragma unroll
        for (int i = 0; i < 4; i++) {
            float2 f = __half22float2(qh[i]);
            qf[2 * i]     = f.x;
            qf[2 * i + 1] = f.y;
        }
    }

    // Logits: 4 contexts per iteration (one per 8-lane group)
    #pragma unroll 4
    for (int c0 = 0; c0 < CTX; c0 += 4) {
        int  c     = c0 + g;
        bool valid = (c < CTX);
        float dot = 0.0f;
        if (valid) {
            float4 kv = *reinterpret_cast<const float4*>(kp[c] + off);
            const __half2* kh = reinterpret_cast<const __half2*>(&kv);
            #pragma unroll
            for (int i = 0; i < 4; i++) {
                float2 f = __half22float2(kh[i]);
                dot += qf[2 * i] * f.x + qf[2 * i + 1] * f.y;
            }
        }
        #pragma unroll
        for (int d = 4; d; d >>= 1)
            dot += __shfl_xor_sync(0xffffffffu, dot, d);
        if (s == 0 && valid)
            logits[h][c] = dot * scale + ((c < 33) ? -dist2[c] * inv2s : gb);
    }
    __syncwarp();

    // softmax over 65 entries (per-warp)
    float l0 = logits[h][lane];
    float l1 = logits[h][lane + 32];
    float l2 = (lane == 0) ? logits[h][64] : -1e30f;
    float m = fmaxf(fmaxf(l0, l1), l2);
    #pragma unroll
    for (int d = 16; d; d >>= 1)
        m = fmaxf(m, __shfl_xor_sync(0xffffffffu, m, d));
    float e0 = __expf(l0 - m);
    float e1 = __expf(l1 - m);
    float e2 = (lane == 0) ? __expf(l2 - m) : 0.0f;
    float sm = e0 + e1 + e2;
    #pragma unroll
    for (int d = 16; d; d >>= 1)
        sm += __shfl_xor_sync(0xffffffffu, sm, d);
    float inv = 1.0f / sm;
    logits[h][lane]      = e0 * inv;
    logits[h][lane + 32] = e1 * inv;
    if (lane == 0) logits[h][64] = e2 * inv;
    __syncwarp();

    // Weighted V sum: group g handles contexts c = 4*i + g; lane holds 8 dims.
    float acc[8];
    #pragma unroll
    for (int i = 0; i < 8; i++) acc[i] = 0.0f;

    #pragma unroll 4
    for (int i = 0; i < 17; i++) {
        int c = 4 * i + g;
        if (c < CTX) {
            float  p  = logits[h][c];
            float4 vv = *reinterpret_cast<const float4*>(vp[c] + off);
            const __half2* vh = reinterpret_cast<const __half2*>(&vv);
            #pragma unroll
            for (int k = 0; k < 4; k++) {
                float2 f = __half22float2(vh[k]);
                acc[2 * k]     += p * f.x;
                acc[2 * k + 1] += p * f.y;
            }
        }
    }
    // Reduce across the 4 groups (same dims, different contexts)
    #pragma unroll
    for (int k = 0; k < 8; k++) {
        acc[k] += __shfl_xor_sync(0xffffffffu, acc[k], 8);
        acc[k] += __shfl_xor_sync(0xffffffffu, acc[k], 16);
    }
    if (g == 0) {
        __half2 hv[4];
        #pragma unroll
        for (int k = 0; k < 4; k++)
            hv[k] = __floats2half2_rn(acc[2 * k], acc[2 * k + 1]);
        *reinterpret_cast<uint4*>(outh + (size_t)bl * DD + off) =
            *reinterpret_cast<const uint4*>(hv);
    }
}

// ---------------------------------------------------------------------------
extern "C" void kernel_launch(void* const* d_in, const int* in_sizes, int n_in,
                              void* d_out, int out_size)
{
    const float* spatial = (const float*)d_in[0];
    const int*   topk    = (const int*)  d_in[1];
    const float* dist    = (const float*)d_in[2];
    const float* glat    = (const float*)d_in[3];
    const float* Wq      = (const float*)d_in[4];
    const float* Wk      = (const float*)d_in[5];
    const float* Wv      = (const float*)d_in[6];
    const float* Wo      = (const float*)d_in[7];
    const float* bo      = (const float*)d_in[8];
    const float* lsig    = (const float*)d_in[9];
    const float* gbias   = (const float*)d_in[10];
    float* out = (float*)d_out;

    __half *Qp, *Kp, *Vp, *Ah, *Kgp, *Vgp;
    __half *sph, *glh, *wqh, *wkh, *wvh, *woh;
    cudaGetSymbolAddress((void**)&Qp,  g_Qh);
    cudaGetSymbolAddress((void**)&Kp,  g_Kh);
    cudaGetSymbolAddress((void**)&Vp,  g_Vh);
    cudaGetSymbolAddress((void**)&Ah,  g_attnh);
    cudaGetSymbolAddress((void**)&Kgp, g_Kgh);
    cudaGetSymbolAddress((void**)&Vgp, g_Vgh);
    cudaGetSymbolAddress((void**)&sph, g_sp_h);
    cudaGetSymbolAddress((void**)&glh, g_gl_h);
    cudaGetSymbolAddress((void**)&wqh, g_Wq_h);
    cudaGetSymbolAddress((void**)&wkh, g_Wk_h);
    cudaGetSymbolAddress((void**)&wvh, g_Wv_h);
    cudaGetSymbolAddress((void**)&woh, g_Wo_h);

    cudaFuncSetAttribute(qkv_gemm, cudaFuncAttributeMaxDynamicSharedMemorySize, GEMM_SMEM);
    cudaFuncSetAttribute(out_gemm, cudaFuncAttributeMaxDynamicSharedMemorySize, GEMM_SMEM);

    // Identify the stream our <<<>>> launches target (the captured one during
    // capture; legacy otherwise).
    cudaStreamCaptureStatus stL = cudaStreamCaptureStatusNone;
    cudaStreamCaptureStatus stP = cudaStreamCaptureStatusNone;
    cudaStreamIsCapturing(cudaStreamLegacy, &stL);
    cudaStreamIsCapturing(cudaStreamPerThread, &stP);
    cudaStream_t smain = (stP == cudaStreamCaptureStatusActive &&
                          stL != cudaStreamCaptureStatusActive)
                         ? cudaStreamPerThread : cudaStreamLegacy;
    cudaStream_t s1 = g_str.s1;

    // Convert all GEMM inputs to fp16 (one pass), then fork.
    dim3 cvt_grid(64, 6);
    to_half_all<<<cvt_grid, 256, 0, smain>>>(
        spatial, sph, BL * DD / 4,
        Wq, wqh, DD * DD / 4,
        Wk, wkh, DD * DD / 4,
        Wv, wvh, DD * DD / 4,
        Wo, woh, DD * DD / 4,
        glat, glh, BB * GG * DD / 4);
    cudaEventRecord(g_str.evF, smain);
    cudaStreamWaitEvent(s1, g_str.evF, 0);

    // Two independent per-batch chains (glat tiles duplicated in each).
    dim3 qkv_grid(4, 17, 3);
    dim3 out_grid(4, 16);
    for (int b = 0; b < 2; b++) {
        cudaStream_t st = (b == 0) ? smain : s1;
        qkv_gemm<<<qkv_grid, 128, GEMM_SMEM, st>>>(
            sph, glh, wqh, wkh, wvh, Qp, Kp, Vp, Kgp, Vgp, b * 16);
        attn_kernel<<<2048, 256, 0, st>>>(
            Qp, Kp, Vp, Kgp, Vgp, topk, dist, lsig, gbias, Ah, b * 2048);
        out_gemm<<<out_grid, 128, GEMM_SMEM, st>>>(
            Ah, woh, bo, out, b * 16);
    }

    // Join chain-1 back into the main stream.
    cudaEventRecord(g_str.evJ, s1);
    cudaStreamWaitEvent(smain, g_str.evJ, 0);
}

// round 17
// speedup vs baseline: 1.1380x; 1.0427x over previous
#include <cuda_runtime.h>
#include <cuda_fp16.h>
#include <mma.h>
#include <cstdint>

using namespace nvcuda;

// Problem constants
#define BB   2
#define LL   2048
#define DD   512
#define KK   32
#define GG   32
#define HH   8
#define DHH  64
#define CTX  65        // 1 + K + G
#define CTXP 68        // padded (multiple of 4)
#define BL   (BB*LL)   // 4096

// Scratch buffers (device globals: no allocation allowed)
__device__ __half g_Qh   [BL * DD];
__device__ __half g_Kh   [BL * DD];
__device__ __half g_Vh   [BL * DD];
__device__ __half g_attnh[BL * DD];          // attention output (fp16)
__device__ __half g_Kgh  [BB * GG * DD];
__device__ __half g_Vgh  [BB * GG * DD];
// fp16 copies of GEMM inputs
__device__ __half g_sp_h[BL * DD];
__device__ __half g_gl_h[BB * GG * DD];
__device__ __half g_Wq_h[DD * DD];
__device__ __half g_Wk_h[DD * DD];
__device__ __half g_Wv_h[DD * DD];
__device__ __half g_Wo_h[DD * DD];

// ---------------------------------------------------------------------------
// fp32 -> fp16 converter for all 6 GEMM inputs (blockIdx.y selects segment)
// n counts are in float4 (4-element) units.
// ---------------------------------------------------------------------------
__global__ __launch_bounds__(256)
void to_half_all(const float* s0, __half* d0, int n0,
                 const float* s1, __half* d1, int n1,
                 const float* s2, __half* d2, int n2,
                 const float* s3, __half* d3, int n3,
                 const float* s4, __half* d4, int n4,
                 const float* s5, __half* d5, int n5)
{
    const float* src; __half* dst; int n;
    switch (blockIdx.y) {
        case 0: src = s0; dst = d0; n = n0; break;
        case 1: src = s1; dst = d1; n = n1; break;
        case 2: src = s2; dst = d2; n = n2; break;
        case 3: src = s3; dst = d3; n = n3; break;
        case 4: src = s4; dst = d4; n = n4; break;
        default: src = s5; dst = d5; n = n5; break;
    }
    int stride = gridDim.x * blockDim.x;
    for (int i = blockIdx.x * blockDim.x + threadIdx.x; i < n; i += stride) {
        float4 v = reinterpret_cast<const float4*>(src)[i];
        __half2* d2p = reinterpret_cast<__half2*>(dst) + i * 2;
        d2p[0] = __floats2half2_rn(v.x, v.y);
        d2p[1] = __floats2half2_rn(v.z, v.w);
    }
}

// ---------------------------------------------------------------------------
// cp.async helpers
// ---------------------------------------------------------------------------
__device__ __forceinline__ void cp_async16(void* smem_dst, const void* gsrc) {
    unsigned int sa = (unsigned int)__cvta_generic_to_shared(smem_dst);
    asm volatile("cp.async.cg.shared.global [%0], [%1], 16;\n" :: "r"(sa), "l"(gsrc));
}
__device__ __forceinline__ void cp_commit() {
    asm volatile("cp.async.commit_group;\n" ::);
}
template <int N>
__device__ __forceinline__ void cp_wait() {
    asm volatile("cp.async.wait_group %0;\n" :: "n"(N));
}

// ---------------------------------------------------------------------------
// fp16 GEMM core (R11 proven config):
// C[0:64, n0:n0+128] = A[0:64, 0:512] @ W[512,512]
// BM=64, BN=128, BK=32, 3-stage cp.async pipeline, 128 threads (4 warps 2x2),
// warp tile 32x64 (2x4 wmma fp16 m16n16k16, fp32 accum). 4 CTAs/SM.
// ---------------------------------------------------------------------------
constexpr int ASTR_H = 40;    // As row stride (halves): 32 + 8 pad
constexpr int BSTR_H = 136;   // Bs row stride (halves): 128 + 8 pad
constexpr int STAGE_HALVES = 64 * ASTR_H + 32 * BSTR_H;    // 6912
constexpr int GEMM_SMEM = 3 * STAGE_HALVES * 2;            // 41472 bytes
constexpr int CSTR = 132;     // epilogue float staging stride

__device__ __forceinline__ void issue_stage_h(
    __half* stage, const __half* __restrict__ A, const __half* __restrict__ W,
    int n0, int k0, int tid)
{
    __half* As = stage;
    __half* Bs = stage + 64 * ASTR_H;
    #pragma unroll
    for (int t = 0; t < 2; t++) {                 // A: 64 rows x 4 chunks(8h)
        int j = tid + t * 128;
        int r = j >> 2, c = (j & 3) << 3;
        cp_async16(&As[r * ASTR_H + c], &A[(size_t)r * 512 + k0 + c]);
    }
    #pragma unroll
    for (int t = 0; t < 4; t++) {                 // B: 32 rows x 16 chunks(8h)
        int j = tid + t * 128;
        int rb = j >> 4, cb = (j & 15) << 3;
        cp_async16(&Bs[rb * BSTR_H + cb], &W[(size_t)(k0 + rb) * 512 + n0 + cb]);
    }
}

__device__ __forceinline__ void gemm_core_h(
    const __half* __restrict__ A, const __half* __restrict__ W,
    float* __restrict__ Cf, __half* __restrict__ Ch,
    const float* __restrict__ bias, int n0)
{
    extern __shared__ __align__(16) __half hsmem[];
    const int tid    = threadIdx.x;
    const int wid    = tid >> 5;
    const int warp_m = wid >> 1;     // 0..1 -> rows warp_m*32
    const int warp_n = wid & 1;      // 0..1 -> cols warp_n*64

    wmma::fragment<wmma::accumulator, 16, 16, 16, float> acc[2][4];
    #pragma unroll
    for (int i = 0; i < 2; i++)
        #pragma unroll
        for (int j = 0; j < 4; j++)
            wmma::fill_fragment(acc[i][j], 0.0f);

    #pragma unroll
    for (int s = 0; s < 2; s++) {
        issue_stage_h(hsmem + s * STAGE_HALVES, A, W, n0, s * 32, tid);
        cp_commit();
    }

    for (int it = 0; it < 16; it++) {
        cp_wait<1>();          // stage `it` resident
        __syncthreads();       // also guards buffer (it+2)%3 reuse
        if (it + 2 < 16)
            issue_stage_h(hsmem + ((it + 2) % 3) * STAGE_HALVES, A, W,
                          n0, (it + 2) * 32, tid);
        cp_commit();           // one group per iter keeps counts aligned

        __half* As = hsmem + (it % 3) * STAGE_HALVES;
        __half* Bs = As + 64 * ASTR_H;
        #pragma unroll
        for (int ks = 0; ks < 2; ks++) {
            wmma::fragment<wmma::matrix_a, 16, 16, 16, half, wmma::row_major> af[2];
            wmma::fragment<wmma::matrix_b, 16, 16, 16, half, wmma::row_major> bf[4];
            wmma::load_matrix_sync(af[0], &As[(warp_m * 32     ) * ASTR_H + ks * 16], ASTR_H);
            wmma::load_matrix_sync(af[1], &As[(warp_m * 32 + 16) * ASTR_H + ks * 16], ASTR_H);
            #pragma unroll
            for (int j = 0; j < 4; j++)
                wmma::load_matrix_sync(bf[j], &Bs[(ks * 16) * BSTR_H + warp_n * 64 + j * 16], BSTR_H);
            #pragma unroll
            for (int i = 0; i < 2; i++)
                #pragma unroll
                for (int j = 0; j < 4; j++)
                    wmma::mma_sync(acc[i][j], af[i], bf[j], acc[i][j]);
        }
    }
    __syncthreads();   // all compute done before epilogue smem reuse

    // Stage via smem (reuse pipeline buffer as float[64][CSTR])
    float (*Cs)[CSTR] = reinterpret_cast<float(*)[CSTR]>(hsmem);
    #pragma unroll
    for (int i = 0; i < 2; i++)
        #pragma unroll
        for (int j = 0; j < 4; j++)
            wmma::store_matrix_sync(
                &Cs[warp_m * 32 + i * 16][warp_n * 64 + j * 16],
                acc[i][j], CSTR, wmma::mem_row_major);
    __syncthreads();

    const int n4 = 64 * 32;                // 64 rows x 128 floats in float4 units
    if (Ch != nullptr) {
        for (int lin = tid; lin < n4; lin += 128) {
            int r = lin >> 5, c4 = (lin & 31) << 2;
            float4 v = *reinterpret_cast<const float4*>(&Cs[r][c4]);
            __half2* dst = reinterpret_cast<__half2*>(&Ch[(size_t)r * 512 + n0 + c4]);
            dst[0] = __floats2half2_rn(v.x, v.y);
            dst[1] = __floats2half2_rn(v.z, v.w);
        }
    } else {
        for (int lin = tid; lin < n4; lin += 128) {
            int r = lin >> 5, c4 = (lin & 31) << 2;
            float4 v = *reinterpret_cast<const float4*>(&Cs[r][c4]);
            v.x += bias[n0 + c4 + 0];
            v.y += bias[n0 + c4 + 1];
            v.z += bias[n0 + c4 + 2];
            v.w += bias[n0 + c4 + 3];
            *reinterpret_cast<float4*>(&Cf[(size_t)r * 512 + n0 + c4]) = v;
        }
    }
}

// Fused Q/K/V projection (+ global-latent K/V). grid = (4, 65, 3)
__global__ __launch_bounds__(128, 4)
void qkv_gemm(const __half* __restrict__ spatial, const __half* __restrict__ glat,
              const __half* __restrict__ Wq, const __half* __restrict__ Wk,
              const __half* __restrict__ Wv,
              __half* __restrict__ Q, __half* __restrict__ K, __half* __restrict__ V,
              __half* __restrict__ Kg, __half* __restrict__ Vg)
{
    const int z = blockIdx.z, y = blockIdx.y;
    const __half* W = (z == 0) ? Wq : (z == 1) ? Wk : Wv;
    if (y < 64) {
        const __half* A = spatial + (size_t)y * 64 * 512;
        __half* C = ((z == 0) ? Q : (z == 1) ? K : V) + (size_t)y * 64 * 512;
        gemm_core_h(A, W, nullptr, C, nullptr, blockIdx.x * 128);
    } else {
        if (z == 0) return;
        gemm_core_h(glat, W, nullptr, (z == 1) ? Kg : Vg, nullptr,
                    blockIdx.x * 128);
    }
}

// Output projection with bias. grid = (4, 64)
__global__ __launch_bounds__(128, 4)
void out_gemm(const __half* __restrict__ A, const __half* __restrict__ W,
              const float* __restrict__ bias, float* __restrict__ C)
{
    gemm_core_h(A + (size_t)blockIdx.y * 64 * 512, W,
                C + (size_t)blockIdx.y * 64 * 512, nullptr, bias,
                blockIdx.x * 128);
}

// ---------------------------------------------------------------------------
// Gather attention: one block per (b,l), one warp per head.
// 8-lane groups, 16B loads; contexts padded to 68 for branch-free loops
// (pad entries alias a valid Kg row; their softmax weight is forced to 0).
// ---------------------------------------------------------------------------
__global__ __launch_bounds__(256)
void attn_kernel(const __half* __restrict__ Q,   const __half* __restrict__ Ksp,
                 const __half* __restrict__ Vsp, const __half* __restrict__ Kg,
                 const __half* __restrict__ Vg,  const int*    __restrict__ topk,
                 const float*  __restrict__ dist,
                 const float*  __restrict__ log_sigma,
                 const float*  __restrict__ gbias_p,
                 __half* __restrict__ outh)
{
    const int bl   = blockIdx.x;
    const int b    = bl >> 11;            // L = 2048
    const int tid  = threadIdx.x;
    const int h    = tid >> 5;
    const int lane = tid & 31;
    const int g    = lane >> 3;           // group 0..3
    const int s    = lane & 7;            // sublane 0..7

    __shared__ const __half* kp[CTXP];
    __shared__ const __half* vp[CTXP];
    __shared__ float dist2[33];
    __shared__ float logits[HH][CTXP];

    if (tid < CTXP) {
        int c = tid;
        const __half *kq, *vq;
        if (c == 0) {
            kq = Ksp + (size_t)bl * DD;
            vq = Vsp + (size_t)bl * DD;
        } else if (c < 33) {
            int r = b * LL + topk[(size_t)bl * KK + (c - 1)];
            kq = Ksp + (size_t)r * DD;
            vq = Vsp + (size_t)r * DD;
        } else if (c < CTX) {
            int r = b * GG + (c - 33);
            kq = Kg + (size_t)r * DD;
            vq = Vg + (size_t)r * DD;
        } else {                          // pad: any valid row, weight forced 0
            kq = Kg + (size_t)(b * GG) * DD;
            vq = Vg + (size_t)(b * GG) * DD;
        }
        kp[c] = kq;
        vp[c] = vq;
        if (c < 33) {
            float d = (c == 0) ? 0.0f : dist[(size_t)bl * KK + (c - 1)];
            dist2[c] = d * d;
        }
    }
    __syncthreads();

    const float inv2s = 0.5f * __expf(-2.0f * log_sigma[h]);  // 1/(2*sigma^2)
    const float gb    = *gbias_p;
    const float scale = 0.125f;                               // 64^-0.5
    const int   off   = h * DHH + s * 8;    // 8-half slice for this sublane

    // Q slice: 8 halves -> 8 floats
    float qf[8];
    {
        float4 qv = *reinterpret_cast<const float4*>(Q + (size_t)bl * DD + off);
        const __half2* qh = reinterpret_cast<const __half2*>(&qv);
        #pragma unroll
        for (int i = 0; i < 4; i++) {
            float2 f = __half22float2(qh[i]);
            qf[2 * i]     = f.x;
            qf[2 * i + 1] = f.y;
        }
    }

    // Logits: 4 contexts per iteration (one per 8-lane group), branch-free
    #pragma unroll 4
    for (int c0 = 0; c0 < CTXP; c0 += 4) {
        int c = c0 + g;
        float4 kv = *reinterpret_cast<const float4*>(kp[c] + off);
        const __half2* kh = reinterpret_cast<const __half2*>(&kv);
        float dot = 0.0f;
        #pragma unroll
        for (int i = 0; i < 4; i++) {
            float2 f = __half22float2(kh[i]);
            dot += qf[2 * i] * f.x + qf[2 * i + 1] * f.y;
        }
        #pragma unroll
        for (int d = 4; d; d >>= 1)
            dot += __shfl_xor_sync(0xffffffffu, dot, d);
        if (s == 0)
            logits[h][c] = dot * scale + ((c < 33) ? -dist2[c] * inv2s : gb);
    }
    __syncwarp();

    // softmax over 65 entries (per-warp); pad entries forced to prob 0
    float l0 = logits[h][lane];
    float l1 = logits[h][lane + 32];
    float l2 = (lane == 0) ? logits[h][64] : -1e30f;
    float m = fmaxf(fmaxf(l0, l1), l2);
    #pragma unroll
    for (int d = 16; d; d >>= 1)
        m = fmaxf(m, __shfl_xor_sync(0xffffffffu, m, d));
    float e0 = __expf(l0 - m);
    float e1 = __expf(l1 - m);
    float e2 = (lane == 0) ? __expf(l2 - m) : 0.0f;
    float sm = e0 + e1 + e2;
    #pragma unroll
    for (int d = 16; d; d >>= 1)
        sm += __shfl_xor_sync(0xffffffffu, sm, d);
    float inv = 1.0f / sm;
    logits[h][lane]      = e0 * inv;
    logits[h][lane + 32] = e1 * inv;
    if (lane == 0) {
        logits[h][64] = e2 * inv;
        logits[h][65] = 0.0f;
        logits[h][66] = 0.0f;
        logits[h][67] = 0.0f;
    }
    __syncwarp();

    // Weighted V sum: group g handles contexts c = 4*i + g; lane holds 8 dims.
    float acc[8];
    #pragma unroll
    for (int i = 0; i < 8; i++) acc[i] = 0.0f;

    #pragma unroll 4
    for (int i = 0; i < CTXP / 4; i++) {
        int c = 4 * i + g;
        float  p  = logits[h][c];
        float4 vv = *reinterpret_cast<const float4*>(vp[c] + off);
        const __half2* vh = reinterpret_cast<const __half2*>(&vv);
        #pragma unroll
        for (int k = 0; k < 4; k++) {
            float2 f = __half22float2(vh[k]);
            acc[2 * k]     += p * f.x;
            acc[2 * k + 1] += p * f.y;
        }
    }
    // Reduce across the 4 groups (same dims, different contexts)
    #pragma unroll
    for (int k = 0; k < 8; k++) {
        acc[k] += __shfl_xor_sync(0xffffffffu, acc[k], 8);
        acc[k] += __shfl_xor_sync(0xffffffffu, acc[k], 16);
    }
    if (g == 0) {
        __half2 hv[4];
        #pragma unroll
        for (int k = 0; k < 4; k++)
            hv[k] = __floats2half2_rn(acc[2 * k], acc[2 * k + 1]);
        *reinterpret_cast<uint4*>(outh + (size_t)bl * DD + off) =
            *reinterpret_cast<const uint4*>(hv);
    }
}

// ---------------------------------------------------------------------------
extern "C" void kernel_launch(void* const* d_in, const int* in_sizes, int n_in,
                              void* d_out, int out_size)
{
    const float* spatial = (const float*)d_in[0];
    const int*   topk    = (const int*)  d_in[1];
    const float* dist    = (const float*)d_in[2];
    const float* glat    = (const float*)d_in[3];
    const float* Wq      = (const float*)d_in[4];
    const float* Wk      = (const float*)d_in[5];
    const float* Wv      = (const float*)d_in[6];
    const float* Wo      = (const float*)d_in[7];
    const float* bo      = (const float*)d_in[8];
    const float* lsig    = (const float*)d_in[9];
    const float* gbias   = (const float*)d_in[10];
    float* out = (float*)d_out;

    __half *Qp, *Kp, *Vp, *Ah, *Kgp, *Vgp;
    __half *sph, *glh, *wqh, *wkh, *wvh, *woh;
    cudaGetSymbolAddress((void**)&Qp,  g_Qh);
    cudaGetSymbolAddress((void**)&Kp,  g_Kh);
    cudaGetSymbolAddress((void**)&Vp,  g_Vh);
    cudaGetSymbolAddress((void**)&Ah,  g_attnh);
    cudaGetSymbolAddress((void**)&Kgp, g_Kgh);
    cudaGetSymbolAddress((void**)&Vgp, g_Vgh);
    cudaGetSymbolAddress((void**)&sph, g_sp_h);
    cudaGetSymbolAddress((void**)&glh, g_gl_h);
    cudaGetSymbolAddress((void**)&wqh, g_Wq_h);
    cudaGetSymbolAddress((void**)&wkh, g_Wk_h);
    cudaGetSymbolAddress((void**)&wvh, g_Wv_h);
    cudaGetSymbolAddress((void**)&woh, g_Wo_h);

    cudaFuncSetAttribute(qkv_gemm, cudaFuncAttributeMaxDynamicSharedMemorySize, GEMM_SMEM);
    cudaFuncSetAttribute(out_gemm, cudaFuncAttributeMaxDynamicSharedMemorySize, GEMM_SMEM);

    // Convert all GEMM inputs to fp16 (one pass)
    dim3 cvt_grid(64, 6);
    to_half_all<<<cvt_grid, 256>>>(
        spatial, sph, BL * DD / 4,
        Wq, wqh, DD * DD / 4,
        Wk, wkh, DD * DD / 4,
        Wv, wvh, DD * DD / 4,
        Wo, woh, DD * DD / 4,
        glat, glh, BB * GG * DD / 4);

    dim3 qkv_grid(4, 65, 3);
    qkv_gemm<<<qkv_grid, 128, GEMM_SMEM>>>(sph, glh, wqh, wkh, wvh,
                                           Qp, Kp, Vp, Kgp, Vgp);

    attn_kernel<<<BL, 256>>>(Qp, Kp, Vp, Kgp, Vgp, topk, dist, lsig, gbias, Ah);

    dim3 out_grid(4, 64);
    out_gemm<<<out_grid, 128, GEMM_SMEM>>>(Ah, woh, bo, out);
}